// round 9
// baseline (speedup 1.0000x reference)
#include <cuda_runtime.h>
#include <cuda_bf16.h>
#include <math.h>

#define NA 8192
#define NB 32
#define NK 128
#define ND 128
#define NTH 512

// dynamic smem layout (floats)
#define SRE 0            // 16384: a1 / W3 stage / S_re -> FS_re
#define SIM 16384        // 16384: a2 / S_im -> FS_im
#define SFW 32768        // 16384: W2 stage / F / phase-3 c+s tiles
#define SEX 49152        // 6144:  phase-1 c (2048) + s (2048) + h (2048) tiles
#define SMEM_BYTES ((16384*3 + 6144) * 4)   // 221184

__device__ __forceinline__ float ldf(const void* p, long i, int isbf) {
    if (isbf) return __bfloat162float(((const __nv_bfloat16*)p)[i]);
    return ((const float*)p)[i];
}
__device__ __forceinline__ int ldb(const void* p, int i, int b64) {
    if (b64) return (int)(((const long long*)p)[i]);
    return ((const int*)p)[i];
}
__device__ __forceinline__ float gelu_t(float x) {
    float x3 = x * x * x;
    return 0.5f * x * (1.0f + tanhf(0.7978845608028654f * fmaf(0.044715f, x3, x)));
}
// content probes: first 512 bytes only (safe for every candidate buffer)
__device__ static bool is_b32(const int* w) {
    int prev = -1;
    for (int j = 0; j < 128; j++) {
        int v = w[j];
        if (v < 0 || v > 63 || v < prev) return false;
        prev = v;
    }
    return true;
}
__device__ static bool is_b64(const int* w) {
    int prev = -1;
    for (int j = 0; j < 64; j++) {
        int lo = w[2*j], hi = w[2*j+1];
        if (hi != 0 || lo < 0 || lo > 63 || lo < prev) return false;
        prev = lo;
    }
    return true;
}

__global__ void zero_kernel(unsigned int* out, long words) {
    long i = blockIdx.x * (long)blockDim.x + threadIdx.x;
    if (i < words) out[i] = 0u;
}

// mode: 0 = real part fp32 | 1 = fp32 (re,im) pairs | 2 = bf16 (re,im) pairs
__global__ void __launch_bounds__(NTH, 1) fused_kernel(
    const void* kv, const void* pos, const void* h,
    const void* W1, const void* b1, const void* b2, const void* b3,
    const void* c0, const void* c1, const void* c2, const void* batch_direct,
    int mf, void* outp, int mode, long cap_f32)
{
    extern __shared__ float sm[];
    __shared__ float kvs[NK * 3];
    __shared__ float poss[64 * 3];
    __shared__ int sh_isbf, sh_b64, sh_s0, sh_s1;
    __shared__ const void* sh_batch;
    __shared__ const void* sh_W2;
    __shared__ const void* sh_W3;

    int tid = threadIdx.x;
    int b = blockIdx.x;

    if (tid == 0) {
        const void* batch = batch_direct;
        const void* w2 = c0; const void* w3 = c1;
        if (!batch) {                       // 3-way size collision: probe content
            const void* cand[3] = {c0, c1, c2};
            int bi = -1;
            for (int i = 0; i < 3; i++) {
                const int* w = (const int*)cand[i];
                if (is_b32(w) || is_b64(w)) { bi = i; break; }
            }
            if (bi < 0) bi = 2;
            int nw = 0; const void* ws[2] = {0, 0};
            for (int i = 0; i < 3; i++) if (i != bi) ws[nw++] = cand[i];
            w2 = ws[0]; w3 = ws[1]; batch = cand[bi];
        }
        sh_batch = batch; sh_W2 = w2; sh_W3 = w3;
        const int* bw = (const int*)batch;
        int b64 = (is_b64(bw) && !is_b32(bw)) ? 1 : 0;
        sh_b64 = b64;
        int isbf;
        if (mf == 2) isbf = 1;
        else if (mf == 4) isbf = 0;
        else {
            const unsigned short* p16 = (const unsigned short*)pos;
            int hits = 0;
            for (int i = 0; i < 256; i++) {
                int e = (p16[i] >> 7) & 0xFF;
                if (e >= 110 && e <= 135) hits++;
            }
            isbf = (hits > 205);
        }
        sh_isbf = isbf;
        int lo = 0, hi = NA;                 // segment bounds (batch sorted)
        while (lo < hi) { int m = (lo+hi)>>1; if (ldb(batch, m, b64) < b) lo = m+1; else hi = m; }
        int s0v = lo;
        lo = 0; hi = NA;
        while (lo < hi) { int m = (lo+hi)>>1; if (ldb(batch, m, b64) < b+1) lo = m+1; else hi = m; }
        sh_s0 = s0v; sh_s1 = (lo < s0v) ? s0v : lo;
    }
    __syncthreads();
    int isbf = sh_isbf;
    int s0 = sh_s0, s1 = sh_s1;
    const void* W2 = sh_W2; const void* W3 = sh_W3;

    // stage this batch's k-vectors
    for (int i = tid; i < NK * 3; i += NTH)
        kvs[i] = ldf(kv, (long)b * NK * 3 + i, isbf);
    __syncthreads();

    // ==== Phase 0: MLP filter F[k][t] -> SFW ====
    for (int i = tid; i < NK * ND; i += NTH) sm[SFW + i] = ldf(W2, i, isbf);
    for (int i = tid; i < NK * ND; i += NTH) {
        int k = i >> 7, t = i & 127;
        float x = fmaf(kvs[k*3+0], ldf(W1, t, isbf),
                  fmaf(kvs[k*3+1], ldf(W1, ND + t, isbf),
                  fmaf(kvs[k*3+2], ldf(W1, 2*ND + t, isbf), ldf(b1, t, isbf))));
        sm[SRE + i] = gelu_t(x);            // a1
    }
    __syncthreads();
    {   // layer 2: a2 = gelu(a1 @ W2 + b2) -> SIM
        int tt = (tid & 31) * 4;
        int rq = tid >> 5;                  // 16 groups x 8 rows
        float y[4][8];
        for (int i = 0; i < 4; i++) {
            float bv = ldf(b2, tt + i, isbf);
            for (int r = 0; r < 8; r++) y[i][r] = bv;
        }
        for (int j = 0; j < NK; j++) {
            float w0 = sm[SFW + j*ND + tt],     wA = sm[SFW + j*ND + tt + 1],
                  wB = sm[SFW + j*ND + tt + 2], wC = sm[SFW + j*ND + tt + 3];
#pragma unroll
            for (int r = 0; r < 8; r++) {
                float av = sm[SRE + (rq*8 + r)*ND + j];
                y[0][r] = fmaf(w0, av, y[0][r]);
                y[1][r] = fmaf(wA, av, y[1][r]);
                y[2][r] = fmaf(wB, av, y[2][r]);
                y[3][r] = fmaf(wC, av, y[3][r]);
            }
        }
        for (int i = 0; i < 4; i++)
            for (int r = 0; r < 8; r++)
                sm[SIM + (rq*8 + r)*ND + tt + i] = gelu_t(y[i][r]);
    }
    __syncthreads();
    for (int i = tid; i < NK * ND; i += NTH) sm[SRE + i] = ldf(W3, i, isbf);
    __syncthreads();
    {   // layer 3: F = a2 @ W3 + b3 -> SFW (W2 dead)
        int tt = (tid & 31) * 4;
        int rq = tid >> 5;
        float y[4][8];
        for (int i = 0; i < 4; i++) {
            float bv = ldf(b3, tt + i, isbf);
            for (int r = 0; r < 8; r++) y[i][r] = bv;
        }
        for (int j = 0; j < NK; j++) {
            float w0 = sm[SRE + j*ND + tt],     wA = sm[SRE + j*ND + tt + 1],
                  wB = sm[SRE + j*ND + tt + 2], wC = sm[SRE + j*ND + tt + 3];
#pragma unroll
            for (int r = 0; r < 8; r++) {
                float av = sm[SIM + (rq*8 + r)*ND + j];
                y[0][r] = fmaf(w0, av, y[0][r]);
                y[1][r] = fmaf(wA, av, y[1][r]);
                y[2][r] = fmaf(wB, av, y[2][r]);
                y[3][r] = fmaf(wC, av, y[3][r]);
            }
        }
        __syncthreads();
        for (int i = 0; i < 4; i++)
            for (int r = 0; r < 8; r++)
                sm[SFW + (rq*8 + r)*ND + tt + i] = y[i][r];
    }
    __syncthreads();

    // ==== Phase 1: S_re/S_im accumulation -> SRE/SIM ====
    {
        int dq = tid & 31, kq = tid >> 5;
        int d0 = dq * 4, k0 = kq * 8;
        float aR[4][8], aI[4][8];
#pragma unroll
        for (int i = 0; i < 4; i++)
#pragma unroll
            for (int j = 0; j < 8; j++) { aR[i][j] = 0.f; aI[i][j] = 0.f; }

        for (int n0 = s0; n0 < s1; n0 += 16) {
            int cnt = min(16, s1 - n0);
            for (int i = tid; i < cnt * 3; i += NTH)
                poss[i] = ldf(pos, (long)(n0 + i/3) * 3 + i%3, isbf);
            __syncthreads();
            for (int idx = tid; idx < cnt * NK; idx += NTH) {
                int a = idx >> 7, k = idx & 127;
                float th = fmaf(poss[a*3], kvs[k*3],
                           fmaf(poss[a*3+1], kvs[k*3+1], poss[a*3+2]*kvs[k*3+2]));
                float sv, cv; sincosf(th, &sv, &cv);
                sm[SEX + idx] = cv;
                sm[SEX + 2048 + idx] = sv;
            }
            for (int idx = tid; idx < cnt * ND; idx += NTH) {
                int a = idx >> 7, d = idx & 127;
                sm[SEX + 4096 + idx] = ldf(h, (long)(n0 + a) * ND + d, isbf);
            }
            __syncthreads();
            for (int a = 0; a < cnt; a++) {
                float hv[4];
#pragma unroll
                for (int i = 0; i < 4; i++) hv[i] = sm[SEX + 4096 + a*ND + d0 + i];
#pragma unroll
                for (int j = 0; j < 8; j++) {
                    float c = sm[SEX + a*NK + k0 + j];
                    float s = sm[SEX + 2048 + a*NK + k0 + j];
#pragma unroll
                    for (int i = 0; i < 4; i++) {
                        aR[i][j] = fmaf(c, hv[i], aR[i][j]);
                        aI[i][j] = fmaf(-s, hv[i], aI[i][j]);
                    }
                }
            }
            __syncthreads();
        }
#pragma unroll
        for (int j = 0; j < 8; j++)
#pragma unroll
            for (int i = 0; i < 4; i++) {
                sm[SRE + (k0 + j)*ND + d0 + i] = aR[i][j];
                sm[SIM + (k0 + j)*ND + d0 + i] = aI[i][j];
            }
    }
    __syncthreads();
    // FS = F * S in place (F in SFW then dead)
    for (int i = tid; i < NK * ND; i += NTH) {
        float f = sm[SFW + i];
        sm[SRE + i] *= f;
        sm[SIM + i] *= f;
    }
    __syncthreads();

    // ==== Phase 3: out[a][d] = sum_k e^{+i th} FS ====
    {
        int dq = tid & 31, aq = tid >> 5;
        int d0 = dq * 4, a0 = aq * 4;
        for (int n0 = s0; n0 < s1; n0 += 64) {
            int cnt = min(64, s1 - n0);
            for (int i = tid; i < cnt * 3; i += NTH)
                poss[i] = ldf(pos, (long)(n0 + i/3) * 3 + i%3, isbf);
            __syncthreads();
            for (int idx = tid; idx < cnt * NK; idx += NTH) {
                int a = idx >> 7, k = idx & 127;
                float th = fmaf(poss[a*3], kvs[k*3],
                           fmaf(poss[a*3+1], kvs[k*3+1], poss[a*3+2]*kvs[k*3+2]));
                float sv, cv; sincosf(th, &sv, &cv);
                sm[SFW + idx] = cv;                // c tile [64][128]
                sm[SFW + 8192 + idx] = sv;         // s tile
            }
            __syncthreads();
            float oR[4][4], oI[4][4];
#pragma unroll
            for (int u = 0; u < 4; u++)
#pragma unroll
                for (int i = 0; i < 4; i++) { oR[u][i] = 0.f; oI[u][i] = 0.f; }
            for (int k = 0; k < NK; k++) {
                float fr[4], fi[4];
#pragma unroll
                for (int i = 0; i < 4; i++) {
                    fr[i] = sm[SRE + k*ND + d0 + i];
                    fi[i] = sm[SIM + k*ND + d0 + i];
                }
#pragma unroll
                for (int u = 0; u < 4; u++) {
                    float c = sm[SFW + (a0 + u)*NK + k];
                    float s = sm[SFW + 8192 + (a0 + u)*NK + k];
#pragma unroll
                    for (int i = 0; i < 4; i++) {
                        oR[u][i] = fmaf(c, fr[i], oR[u][i]);
                        oR[u][i] = fmaf(-s, fi[i], oR[u][i]);
                        oI[u][i] = fmaf(s, fr[i], oI[u][i]);
                        oI[u][i] = fmaf(c, fi[i], oI[u][i]);
                    }
                }
            }
            for (int u = 0; u < 4; u++) {
                int a = a0 + u;
                if (a < cnt) {
                    long row = (long)(n0 + a) * ND;
                    for (int i = 0; i < 4; i++) {
                        long idx = row + d0 + i;       // complex element index
                        if (mode == 0) {               // real part fp32
                            if (idx < cap_f32)
                                ((float*)outp)[idx] = oR[u][i];
                        } else if (mode == 1) {        // fp32 interleaved pairs
                            if (2*idx + 1 < cap_f32)
                                ((float2*)outp)[idx] = make_float2(oR[u][i], oI[u][i]);
                        } else {                       // bf16 interleaved pairs
                            if (idx + 1 <= cap_f32) {  // cap_f32 = bf16x2 capacity
                                __nv_bfloat162 v;
                                v.x = __float2bfloat16(oR[u][i]);
                                v.y = __float2bfloat16(oI[u][i]);
                                ((__nv_bfloat162*)outp)[idx] = v;
                            }
                        }
                    }
                }
            }
            __syncthreads();
        }
    }
}

// ---------------------------------------------------------------------------
// Host. mf = size(h)/1048576 in {1 elements, 2 bf16-bytes, 4 fp32-bytes}.
// Output epilogue by out_size (all caps are safe under every interpretation):
//   1048576 -> real part fp32 (4 MB; safe for f32 and c64 allocs)
//   2097152 -> fp32 pairs, 2M floats (8 MB only if capacity allows: elements)
//   8388608 -> fp32 pairs capped 2M floats (bytes)
//   4194304 -> bf16 pairs, 1M bf16x2 (4 MB bytes)
//   else    -> real fp32 capped out_size/4 floats (byte lower bound)
// ---------------------------------------------------------------------------
extern "C" void kernel_launch(void* const* d_in, const int* in_sizes, int n_in,
                              void* d_out, int out_size) {
    long mx = 0;
    for (int i = 0; i < n_in; i++) if ((long)in_sizes[i] > mx) mx = in_sizes[i];
    long mf;
    if (mx == 1048576L) mf = 1;
    else if (mx == 2097152L) mf = 2;
    else if (mx == 4194304L) mf = 4;
    else return;

    const void *kv = 0, *pos = 0, *h = 0, *W1 = 0;
    const void* bias[3] = {0, 0, 0};
    const void* grp[3] = {0, 0, 0};
    const void* extra = 0;
    int nb = 0, ng = 0;
    long extra_sz = (mf == 1) ? 8192 : (mf == 2) ? 65536 : 32768;
    for (int i = 0; i < n_in; i++) {
        long s = in_sizes[i];
        const void* p = d_in[i];
        if (s == 12288L * mf)        kv = p;
        else if (s == 24576L * mf)   pos = p;
        else if (s == 1048576L * mf) h = p;
        else if (s == 384L * mf)     W1 = p;
        else if (s == 128L * mf)   { if (nb < 3) bias[nb++] = p; }
        else if (s == 16384L * mf) { if (ng < 3) grp[ng++] = p; }
        else if (s == extra_sz)      extra = p;
    }
    if (!kv || !pos || !h || !W1 || nb < 3) return;

    const void *c0 = 0, *c1 = 0, *c2 = 0, *bd = 0;
    if (ng == 3)               { c0 = grp[0]; c1 = grp[1]; c2 = grp[2]; }
    else if (ng == 2 && extra) { c0 = grp[0]; c1 = grp[1]; bd = extra; }
    else return;

    int mode; long cap;
    if (out_size == 1048576)      { mode = 0; cap = 1048576L; }
    else if (out_size == 2097152) { mode = 1; cap = 2097152L; }
    else if (out_size == 8388608) { mode = 1; cap = 2097152L; }
    else if (out_size == 4194304) { mode = 2; cap = 1048576L; }   // bf16x2 count
    else                          { mode = 0; cap = (long)out_size / 4; }

    long words = (long)out_size / 4;          // <= capacity bytes under all conventions
    if (words > 0)
        zero_kernel<<<(int)((words + 255) / 256), 256>>>((unsigned int*)d_out, words);

    cudaFuncSetAttribute(fused_kernel,
                         cudaFuncAttributeMaxDynamicSharedMemorySize, SMEM_BYTES);
    fused_kernel<<<NB, NTH, SMEM_BYTES>>>(kv, pos, h, W1, bias[0], bias[1],
                                          bias[2], c0, c1, c2, bd, (int)mf,
                                          d_out, mode, cap);
}

// round 10
// speedup vs baseline: 2.0553x; 2.0553x over previous
#include <cuda_runtime.h>
#include <cuda_bf16.h>
#include <math.h>

#define NA 8192
#define NB 32
#define NK 128
#define ND 128

// Scratch (device globals)
__device__ float g_c[NA * NK];
__device__ float g_s[NA * NK];
__device__ float g_F[NB * NK * ND];
__device__ float g_FSre[NB * NK * ND];
__device__ float g_FSim[NB * NK * ND];
__device__ int   g_seg[NB + 1];

struct DevPtrs {
    const void *kv, *pos, *h, *W1, *b1, *W2, *b2, *W3, *b3, *batch;
    int isbf16;
    int batch64;
};
__device__ DevPtrs g_P;

__device__ __forceinline__ float ldf(const void* p, long i, int isbf) {
    if (isbf) return __bfloat162float(((const __nv_bfloat16*)p)[i]);
    return ((const float*)p)[i];
}
__device__ __forceinline__ int ldb(const void* p, int i, int b64) {
    if (b64) return (int)(((const long long*)p)[i]);
    return ((const int*)p)[i];
}
__device__ __forceinline__ float gelu_t(float x) {
    float x3 = x * x * x;
    return 0.5f * x * (1.0f + tanhf(0.7978845608028654f * fmaf(0.044715f, x3, x)));
}
__device__ static bool is_b32(const int* w) {
    int prev = -1;
    for (int j = 0; j < 128; j++) {
        int v = w[j];
        if (v < 0 || v > 63 || v < prev) return false;
        prev = v;
    }
    return true;
}
__device__ static bool is_b64(const int* w) {
    int prev = -1;
    for (int j = 0; j < 64; j++) {
        int lo = w[2*j], hi = w[2*j+1];
        if (hi != 0 || lo < 0 || lo > 63 || lo < prev) return false;
        prev = lo;
    }
    return true;
}

// ---------------------------------------------------------------------------
// Setup: pointer disambiguation + dtype detection + segment offsets.
// ---------------------------------------------------------------------------
__global__ void setup_kernel(const void* kv, const void* pos, const void* h,
                             const void* W1, const void* b1, const void* b2,
                             const void* b3, const void* c0, const void* c1,
                             const void* c2, const void* batch_direct, int mf) {
    int tid = threadIdx.x;
    if (tid == 0) {
        DevPtrs P;
        P.kv = kv; P.pos = pos; P.h = h; P.W1 = W1;
        P.b1 = b1; P.b2 = b2; P.b3 = b3;
        const void* batch = batch_direct;
        const void* w2 = c0; const void* w3 = c1;
        if (!batch) {
            const void* cand[3] = {c0, c1, c2};
            int bi = -1;
            for (int i = 0; i < 3; i++) {
                const int* w = (const int*)cand[i];
                if (is_b32(w) || is_b64(w)) { bi = i; break; }
            }
            if (bi < 0) bi = 2;
            int nw = 0; const void* ws[2] = {0, 0};
            for (int i = 0; i < 3; i++) if (i != bi) ws[nw++] = cand[i];
            w2 = ws[0]; w3 = ws[1]; batch = cand[bi];
        }
        P.W2 = w2; P.W3 = w3; P.batch = batch;
        const int* bw = (const int*)batch;
        P.batch64 = (is_b64(bw) && !is_b32(bw)) ? 1 : 0;
        if (mf == 2) P.isbf16 = 1;
        else if (mf == 4) P.isbf16 = 0;
        else {
            const unsigned short* p16 = (const unsigned short*)pos;
            int hits = 0;
            for (int i = 0; i < 256; i++) {
                int e = (p16[i] >> 7) & 0xFF;
                if (e >= 110 && e <= 135) hits++;
            }
            P.isbf16 = (hits > 205);
        }
        g_P = P;
    }
    __syncthreads();
    if (tid <= NB) {
        const void* batch = g_P.batch;
        int b64 = g_P.batch64;
        int lo = 0, hi = NA;
        while (lo < hi) {
            int m = (lo + hi) >> 1;
            if (ldb(batch, m, b64) < tid) lo = m + 1; else hi = m;
        }
        if (lo < 0) lo = 0;
        if (lo > NA) lo = NA;
        g_seg[tid] = lo;
    }
}

__global__ void zero_kernel(unsigned int* out, long words) {
    long i = blockIdx.x * (long)blockDim.x + threadIdx.x;
    if (i < words) out[i] = 0u;
}

// ---------------------------------------------------------------------------
// theta: c/s for one atom per block
// ---------------------------------------------------------------------------
__global__ void theta_kernel() {
    const DevPtrs P = g_P;
    int n = blockIdx.x;
    int k = threadIdx.x;
    __shared__ float p[3];
    __shared__ int bsh;
    if (k < 3) p[k] = ldf(P.pos, (long)n * 3 + k, P.isbf16);
    if (k == 0) bsh = ldb(P.batch, n, P.batch64) & 31;
    __syncthreads();
    long base = ((long)bsh * NK + k) * 3;
    float th = fmaf(p[0], ldf(P.kv, base, P.isbf16),
               fmaf(p[1], ldf(P.kv, base + 1, P.isbf16),
                    p[2] * ldf(P.kv, base + 2, P.isbf16)));
    float sv, cv;
    sincosf(th, &sv, &cv);
    g_c[n * NK + k] = cv;
    g_s[n * NK + k] = sv;
}

// ---------------------------------------------------------------------------
// MLP: 8 rows per block, 128 threads (t = output dim)
// ---------------------------------------------------------------------------
__global__ void __launch_bounds__(128) mlp_kernel() {
    const DevPtrs P = g_P;
    int isbf = P.isbf16;
    int row0 = blockIdx.x * 8;
    int t = threadIdx.x;
    __shared__ float kvs[8 * 3];
    __shared__ float a1[8][NK], a2[8][NK];

    if (t < 24) kvs[t] = ldf(P.kv, (long)row0 * 3 + t, isbf);
    float w10 = ldf(P.W1, t, isbf);
    float w11 = ldf(P.W1, NK + t, isbf);
    float w12 = ldf(P.W1, 2 * NK + t, isbf);
    float bv1 = ldf(P.b1, t, isbf);
    __syncthreads();
#pragma unroll
    for (int r = 0; r < 8; r++) {
        float x = fmaf(kvs[r*3], w10, fmaf(kvs[r*3+1], w11,
                  fmaf(kvs[r*3+2], w12, bv1)));
        a1[r][t] = gelu_t(x);
    }
    __syncthreads();
    {
        float y[8];
        float bv = ldf(P.b2, t, isbf);
#pragma unroll
        for (int r = 0; r < 8; r++) y[r] = bv;
#pragma unroll 4
        for (int j = 0; j < NK; j++) {
            float w = ldf(P.W2, (long)j * NK + t, isbf);
#pragma unroll
            for (int r = 0; r < 8; r++) y[r] = fmaf(a1[r][j], w, y[r]);
        }
#pragma unroll
        for (int r = 0; r < 8; r++) a2[r][t] = gelu_t(y[r]);
    }
    __syncthreads();
    {
        float y[8];
        float bv = ldf(P.b3, t, isbf);
#pragma unroll
        for (int r = 0; r < 8; r++) y[r] = bv;
#pragma unroll 4
        for (int j = 0; j < NK; j++) {
            float w = ldf(P.W3, (long)j * NK + t, isbf);
#pragma unroll
            for (int r = 0; r < 8; r++) y[r] = fmaf(a2[r][j], w, y[r]);
        }
#pragma unroll
        for (int r = 0; r < 8; r++) g_F[(long)(row0 + r) * NK + t] = y[r];
    }
}

// ---------------------------------------------------------------------------
// segsum: grid (NB, 8); block covers batch b, 16 k. 256 threads:
// thread owns 4 d x 2 k complex accumulators.
// ---------------------------------------------------------------------------
__global__ void __launch_bounds__(256) segsum_kernel() {
    const DevPtrs P = g_P;
    int isbf = P.isbf16;
    int b = blockIdx.x;
    int k0 = blockIdx.y * 16;
    int tid = threadIdx.x;
    int d0 = (tid & 31) * 4;
    int kq = tid >> 5;              // 8 groups x 2 k
    int s0 = g_seg[b], s1 = g_seg[b + 1];
    if (s1 < s0) s1 = s0;

    __shared__ float csh[32][16], ssh[32][16];
    __shared__ float hsh[32][ND];

    float aR[4][2], aI[4][2];
#pragma unroll
    for (int i = 0; i < 4; i++)
#pragma unroll
        for (int j = 0; j < 2; j++) { aR[i][j] = 0.f; aI[i][j] = 0.f; }

    for (int n0 = s0; n0 < s1; n0 += 32) {
        int cnt = min(32, s1 - n0);
        for (int i = tid; i < cnt * 16; i += 256) {
            int a = i >> 4, kk = i & 15;
            csh[a][kk] = g_c[(n0 + a) * NK + k0 + kk];
            ssh[a][kk] = g_s[(n0 + a) * NK + k0 + kk];
        }
        for (int i = tid; i < cnt * ND; i += 256) {
            int a = i >> 7, d = i & 127;
            hsh[a][d] = ldf(P.h, (long)(n0 + a) * ND + d, isbf);
        }
        __syncthreads();
        for (int a = 0; a < cnt; a++) {
            float hv[4];
#pragma unroll
            for (int i = 0; i < 4; i++) hv[i] = hsh[a][d0 + i];
#pragma unroll
            for (int j = 0; j < 2; j++) {
                float c = csh[a][kq * 2 + j];
                float s = ssh[a][kq * 2 + j];
#pragma unroll
                for (int i = 0; i < 4; i++) {
                    aR[i][j] = fmaf(c, hv[i], aR[i][j]);
                    aI[i][j] = fmaf(-s, hv[i], aI[i][j]);
                }
            }
        }
        __syncthreads();
    }
#pragma unroll
    for (int j = 0; j < 2; j++) {
        long off = ((long)b * NK + k0 + kq * 2 + j) * ND + d0;
#pragma unroll
        for (int i = 0; i < 4; i++) {
            float f = g_F[off + i];
            g_FSre[off + i] = f * aR[i][j];
            g_FSim[off + i] = f * aI[i][j];
        }
    }
}

// ---------------------------------------------------------------------------
// out: grid (NB, 8); 32-atom chunks. 256 threads: thread owns 4 a x 4 d.
// mode 0 = real fp32 | 1 = fp32 pairs | 2 = bf16 pairs
// ---------------------------------------------------------------------------
__global__ void __launch_bounds__(256) out_kernel(void* __restrict__ outp,
                                                  int mode, long cap) {
    int b = blockIdx.x;
    int s0 = g_seg[b], s1 = g_seg[b + 1];
    if (s1 < s0) s1 = s0;
    int tid = threadIdx.x;
    int d0 = (tid & 31) * 4;
    int a0 = (tid >> 5) * 4;

    __shared__ float csh[32][NK], ssh[32][NK];

    const float* FR = g_FSre + (long)b * NK * ND;
    const float* FI = g_FSim + (long)b * NK * ND;

    for (int n0 = s0 + blockIdx.y * 32; n0 < s1; n0 += 8 * 32) {
        int cnt = min(32, s1 - n0);
        for (int i = tid; i < cnt * NK; i += 256) {
            int a = i >> 7, k = i & 127;
            csh[a][k] = g_c[(n0 + a) * NK + k];
            ssh[a][k] = g_s[(n0 + a) * NK + k];
        }
        __syncthreads();

        if (mode == 0) {
            float oR[4][4];
#pragma unroll
            for (int u = 0; u < 4; u++)
#pragma unroll
                for (int i = 0; i < 4; i++) oR[u][i] = 0.f;
#pragma unroll 2
            for (int k = 0; k < NK; k++) {
                float4 fr = *(const float4*)(FR + (long)k * ND + d0);
                float4 fi = *(const float4*)(FI + (long)k * ND + d0);
#pragma unroll
                for (int u = 0; u < 4; u++) {
                    float c = csh[a0 + u][k];
                    float s = ssh[a0 + u][k];
                    oR[u][0] = fmaf(c, fr.x, fmaf(-s, fi.x, oR[u][0]));
                    oR[u][1] = fmaf(c, fr.y, fmaf(-s, fi.y, oR[u][1]));
                    oR[u][2] = fmaf(c, fr.z, fmaf(-s, fi.z, oR[u][2]));
                    oR[u][3] = fmaf(c, fr.w, fmaf(-s, fi.w, oR[u][3]));
                }
            }
#pragma unroll
            for (int u = 0; u < 4; u++) {
                int a = a0 + u;
                if (a < cnt) {
                    long idx = (long)(n0 + a) * ND + d0;
                    if (idx + 4 <= cap) {
                        float4 v = make_float4(oR[u][0], oR[u][1], oR[u][2], oR[u][3]);
                        *(float4*)((float*)outp + idx) = v;
                    }
                }
            }
        } else {
            float oR[4][4], oI[4][4];
#pragma unroll
            for (int u = 0; u < 4; u++)
#pragma unroll
                for (int i = 0; i < 4; i++) { oR[u][i] = 0.f; oI[u][i] = 0.f; }
            for (int k = 0; k < NK; k++) {
                float4 fr = *(const float4*)(FR + (long)k * ND + d0);
                float4 fi = *(const float4*)(FI + (long)k * ND + d0);
#pragma unroll
                for (int u = 0; u < 4; u++) {
                    float c = csh[a0 + u][k];
                    float s = ssh[a0 + u][k];
                    oR[u][0] = fmaf(c, fr.x, fmaf(-s, fi.x, oR[u][0]));
                    oR[u][1] = fmaf(c, fr.y, fmaf(-s, fi.y, oR[u][1]));
                    oR[u][2] = fmaf(c, fr.z, fmaf(-s, fi.z, oR[u][2]));
                    oR[u][3] = fmaf(c, fr.w, fmaf(-s, fi.w, oR[u][3]));
                    oI[u][0] = fmaf(s, fr.x, fmaf(c, fi.x, oI[u][0]));
                    oI[u][1] = fmaf(s, fr.y, fmaf(c, fi.y, oI[u][1]));
                    oI[u][2] = fmaf(s, fr.z, fmaf(c, fi.z, oI[u][2]));
                    oI[u][3] = fmaf(s, fr.w, fmaf(c, fi.w, oI[u][3]));
                }
            }
#pragma unroll
            for (int u = 0; u < 4; u++) {
                int a = a0 + u;
                if (a < cnt) {
                    long row = (long)(n0 + a) * ND;
                    for (int i = 0; i < 4; i++) {
                        long idx = row + d0 + i;
                        if (mode == 1) {
                            if (2 * idx + 1 < cap)
                                ((float2*)outp)[idx] = make_float2(oR[u][i], oI[u][i]);
                        } else {
                            if (idx + 1 <= cap) {
                                __nv_bfloat162 v;
                                v.x = __float2bfloat16(oR[u][i]);
                                v.y = __float2bfloat16(oI[u][i]);
                                ((__nv_bfloat162*)outp)[idx] = v;
                            }
                        }
                    }
                }
            }
        }
        __syncthreads();
    }
}

// ---------------------------------------------------------------------------
extern "C" void kernel_launch(void* const* d_in, const int* in_sizes, int n_in,
                              void* d_out, int out_size) {
    long mx = 0;
    for (int i = 0; i < n_in; i++) if ((long)in_sizes[i] > mx) mx = in_sizes[i];
    long mf;
    if (mx == 1048576L) mf = 1;
    else if (mx == 2097152L) mf = 2;
    else if (mx == 4194304L) mf = 4;
    else return;

    const void *kv = 0, *pos = 0, *h = 0, *W1 = 0;
    const void* bias[3] = {0, 0, 0};
    const void* grp[3] = {0, 0, 0};
    const void* extra = 0;
    int nb = 0, ng = 0;
    long extra_sz = (mf == 1) ? 8192 : (mf == 2) ? 65536 : 32768;
    for (int i = 0; i < n_in; i++) {
        long s = in_sizes[i];
        const void* p = d_in[i];
        if (s == 12288L * mf)        kv = p;
        else if (s == 24576L * mf)   pos = p;
        else if (s == 1048576L * mf) h = p;
        else if (s == 384L * mf)     W1 = p;
        else if (s == 128L * mf)   { if (nb < 3) bias[nb++] = p; }
        else if (s == 16384L * mf) { if (ng < 3) grp[ng++] = p; }
        else if (s == extra_sz)      extra = p;
    }
    if (!kv || !pos || !h || !W1 || nb < 3) return;

    const void *c0 = 0, *c1 = 0, *c2 = 0, *bd = 0;
    if (ng == 3)               { c0 = grp[0]; c1 = grp[1]; c2 = grp[2]; }
    else if (ng == 2 && extra) { c0 = grp[0]; c1 = grp[1]; bd = extra; }
    else return;

    int mode; long cap;
    if (out_size == 1048576)      { mode = 0; cap = 1048576L; }
    else if (out_size == 2097152) { mode = 1; cap = 2097152L; }
    else if (out_size == 8388608) { mode = 1; cap = 2097152L; }
    else if (out_size == 4194304) { mode = 2; cap = 1048576L; }
    else                          { mode = 0; cap = (long)out_size / 4; }

    long words = (long)out_size / 4;
    if (words > 0)
        zero_kernel<<<(int)((words + 255) / 256), 256>>>((unsigned int*)d_out, words);

    setup_kernel<<<1, 64>>>(kv, pos, h, W1, bias[0], bias[1], bias[2],
                            c0, c1, c2, bd, (int)mf);
    theta_kernel<<<NA, NK>>>();
    mlp_kernel<<<NB * NK / 8, 128>>>();
    segsum_kernel<<<dim3(NB, 8), 256>>>();
    out_kernel<<<dim3(NB, 8), 256>>>(d_out, mode, cap);
}

// round 11
// speedup vs baseline: 2.1461x; 1.0442x over previous
#include <cuda_runtime.h>
#include <cuda_bf16.h>
#include <math.h>

#define NA 8192
#define NB 32
#define NK 128
#define ND 128

__device__ float g_c[NA * NK];
__device__ float g_s[NA * NK];
__device__ float g_F[NB * NK * ND];
__device__ float g_FSre[NB * NK * ND];
__device__ float g_FSim[NB * NK * ND];
__device__ int   g_seg[NB + 1];

struct DevPtrs {
    const void *kv, *pos, *h, *W1, *b1, *W2, *b2, *W3, *b3, *batch;
    int isbf16;
    int batch64;
};
__device__ DevPtrs g_P;

__device__ __forceinline__ float ldf(const void* p, long i, int isbf) {
    if (isbf) return __bfloat162float(((const __nv_bfloat16*)p)[i]);
    return ((const float*)p)[i];
}
__device__ __forceinline__ int ldb(const void* p, int i, int b64) {
    if (b64) return (int)(((const long long*)p)[i]);
    return ((const int*)p)[i];
}
__device__ __forceinline__ float gelu_t(float x) {
    float x3 = x * x * x;
    return 0.5f * x * (1.0f + tanhf(0.7978845608028654f * fmaf(0.044715f, x3, x)));
}
__device__ static bool is_b32(const int* w) {
    int prev = -1;
    for (int j = 0; j < 128; j++) {
        int v = w[j];
        if (v < 0 || v > 63 || v < prev) return false;
        prev = v;
    }
    return true;
}
__device__ static bool is_b64(const int* w) {
    int prev = -1;
    for (int j = 0; j < 64; j++) {
        int lo = w[2*j], hi = w[2*j+1];
        if (hi != 0 || lo < 0 || lo > 63 || lo < prev) return false;
        prev = lo;
    }
    return true;
}

__global__ void setup_kernel(const void* kv, const void* pos, const void* h,
                             const void* W1, const void* b1, const void* b2,
                             const void* b3, const void* c0, const void* c1,
                             const void* c2, const void* batch_direct, int mf) {
    int tid = threadIdx.x;
    if (tid == 0) {
        DevPtrs P;
        P.kv = kv; P.pos = pos; P.h = h; P.W1 = W1;
        P.b1 = b1; P.b2 = b2; P.b3 = b3;
        const void* batch = batch_direct;
        const void* w2 = c0; const void* w3 = c1;
        if (!batch) {
            const void* cand[3] = {c0, c1, c2};
            int bi = -1;
            for (int i = 0; i < 3; i++) {
                const int* w = (const int*)cand[i];
                if (is_b32(w) || is_b64(w)) { bi = i; break; }
            }
            if (bi < 0) bi = 2;
            int nw = 0; const void* ws[2] = {0, 0};
            for (int i = 0; i < 3; i++) if (i != bi) ws[nw++] = cand[i];
            w2 = ws[0]; w3 = ws[1]; batch = cand[bi];
        }
        P.W2 = w2; P.W3 = w3; P.batch = batch;
        const int* bw = (const int*)batch;
        P.batch64 = (is_b64(bw) && !is_b32(bw)) ? 1 : 0;
        if (mf == 2) P.isbf16 = 1;
        else if (mf == 4) P.isbf16 = 0;
        else {
            const unsigned short* p16 = (const unsigned short*)pos;
            int hits = 0;
            for (int i = 0; i < 256; i++) {
                int e = (p16[i] >> 7) & 0xFF;
                if (e >= 110 && e <= 135) hits++;
            }
            P.isbf16 = (hits > 205);
        }
        g_P = P;
    }
    __syncthreads();
    if (tid <= NB) {
        const void* batch = g_P.batch;
        int b64 = g_P.batch64;
        int lo = 0, hi = NA;
        while (lo < hi) {
            int m = (lo + hi) >> 1;
            if (ldb(batch, m, b64) < tid) lo = m + 1; else hi = m;
        }
        if (lo < 0) lo = 0;
        if (lo > NA) lo = NA;
        g_seg[tid] = lo;
    }
}

__global__ void zero_kernel(unsigned int* out, long words) {
    long i = blockIdx.x * (long)blockDim.x + threadIdx.x;
    if (i < words) out[i] = 0u;
}

// ---------------------------------------------------------------------------
// theta: one atom per block
// ---------------------------------------------------------------------------
__global__ void theta_kernel() {
    const DevPtrs P = g_P;
    int n = blockIdx.x;
    int k = threadIdx.x;
    __shared__ float p[3];
    __shared__ int bsh;
    if (k < 3) p[k] = ldf(P.pos, (long)n * 3 + k, P.isbf16);
    if (k == 0) bsh = ldb(P.batch, n, P.batch64) & 31;
    __syncthreads();
    long base = ((long)bsh * NK + k) * 3;
    float th = fmaf(p[0], ldf(P.kv, base, P.isbf16),
               fmaf(p[1], ldf(P.kv, base + 1, P.isbf16),
                    p[2] * ldf(P.kv, base + 2, P.isbf16)));
    float sv, cv;
    sincosf(th, &sv, &cv);
    g_c[n * NK + k] = cv;
    g_s[n * NK + k] = sv;
}

// ---------------------------------------------------------------------------
// MLP v2: 16 rows per block (256 blocks), 128 threads, weights in 64 KB smem,
// activations in [row][j] layout read as broadcast float4.
// ---------------------------------------------------------------------------
#define MLP_ROWS 16
__global__ void __launch_bounds__(128) mlp_kernel() {
    extern __shared__ float wsh[];            // [NK][NK] = 64 KB
    __shared__ float a1[MLP_ROWS][NK];
    __shared__ float a2[MLP_ROWS][NK];
    __shared__ float kvs[MLP_ROWS * 3];

    const DevPtrs P = g_P;
    int isbf = P.isbf16;
    int row0 = blockIdx.x * MLP_ROWS;
    int t = threadIdx.x;

    if (t < MLP_ROWS * 3) kvs[t] = ldf(P.kv, (long)row0 * 3 + t, isbf);

    // stage W2
    if (isbf) {
        const __nv_bfloat16* w = (const __nv_bfloat16*)P.W2;
        for (int i = t; i < NK * NK; i += 128) wsh[i] = __bfloat162float(w[i]);
    } else {
        const float4* w = (const float4*)P.W2;
        float4* ws4 = (float4*)wsh;
        for (int i = t; i < NK * NK / 4; i += 128) ws4[i] = w[i];
    }

    // layer 1
    {
        float w10 = ldf(P.W1, t, isbf);
        float w11 = ldf(P.W1, NK + t, isbf);
        float w12 = ldf(P.W1, 2 * NK + t, isbf);
        float bv1 = ldf(P.b1, t, isbf);
        __syncthreads();   // kvs ready (also covers W2 stage)
#pragma unroll
        for (int r = 0; r < MLP_ROWS; r++) {
            float x = fmaf(kvs[r*3], w10, fmaf(kvs[r*3+1], w11,
                      fmaf(kvs[r*3+2], w12, bv1)));
            a1[r][t] = gelu_t(x);
        }
    }
    __syncthreads();

    // layer 2: a2 = gelu(a1 @ W2 + b2)
    {
        float y[MLP_ROWS];
        float bv = ldf(P.b2, t, isbf);
#pragma unroll
        for (int r = 0; r < MLP_ROWS; r++) y[r] = bv;
        for (int j = 0; j < NK; j += 4) {
            float w0 = wsh[j*NK + t], w1 = wsh[(j+1)*NK + t],
                  w2 = wsh[(j+2)*NK + t], w3 = wsh[(j+3)*NK + t];
#pragma unroll
            for (int r = 0; r < MLP_ROWS; r++) {
                float4 av = *(const float4*)&a1[r][j];   // broadcast
                y[r] = fmaf(av.x, w0, y[r]);
                y[r] = fmaf(av.y, w1, y[r]);
                y[r] = fmaf(av.z, w2, y[r]);
                y[r] = fmaf(av.w, w3, y[r]);
            }
        }
#pragma unroll
        for (int r = 0; r < MLP_ROWS; r++) a2[r][t] = gelu_t(y[r]);
    }
    __syncthreads();

    // stage W3
    if (isbf) {
        const __nv_bfloat16* w = (const __nv_bfloat16*)P.W3;
        for (int i = t; i < NK * NK; i += 128) wsh[i] = __bfloat162float(w[i]);
    } else {
        const float4* w = (const float4*)P.W3;
        float4* ws4 = (float4*)wsh;
        for (int i = t; i < NK * NK / 4; i += 128) ws4[i] = w[i];
    }
    __syncthreads();

    // layer 3: F = a2 @ W3 + b3
    {
        float y[MLP_ROWS];
        float bv = ldf(P.b3, t, isbf);
#pragma unroll
        for (int r = 0; r < MLP_ROWS; r++) y[r] = bv;
        for (int j = 0; j < NK; j += 4) {
            float w0 = wsh[j*NK + t], w1 = wsh[(j+1)*NK + t],
                  w2 = wsh[(j+2)*NK + t], w3 = wsh[(j+3)*NK + t];
#pragma unroll
            for (int r = 0; r < MLP_ROWS; r++) {
                float4 av = *(const float4*)&a2[r][j];
                y[r] = fmaf(av.x, w0, y[r]);
                y[r] = fmaf(av.y, w1, y[r]);
                y[r] = fmaf(av.z, w2, y[r]);
                y[r] = fmaf(av.w, w3, y[r]);
            }
        }
#pragma unroll
        for (int r = 0; r < MLP_ROWS; r++)
            g_F[(long)(row0 + r) * NK + t] = y[r];
    }
}

// ---------------------------------------------------------------------------
// segsum v2: grid (NB, 8), 512 threads. Thread owns 4d x 1k.
// c,s warp-uniform broadcasts; h via float4 LDS.
// ---------------------------------------------------------------------------
__global__ void __launch_bounds__(512) segsum_kernel() {
    const DevPtrs P = g_P;
    int isbf = P.isbf16;
    int b = blockIdx.x;
    int k0 = blockIdx.y * 16;
    int tid = threadIdx.x;
    int d0 = (tid & 31) * 4;
    int kq = tid >> 5;                 // 0..15, warp-uniform
    int s0 = g_seg[b], s1 = g_seg[b + 1];
    if (s1 < s0) s1 = s0;

    __shared__ float csh[32][16], ssh[32][16];
    __shared__ float hsh[32][ND];

    float aR[4] = {0.f, 0.f, 0.f, 0.f};
    float aI[4] = {0.f, 0.f, 0.f, 0.f};

    for (int n0 = s0; n0 < s1; n0 += 32) {
        int cnt = min(32, s1 - n0);
        if (tid < cnt * 16) {
            int a = tid >> 4, kk = tid & 15;
            csh[a][kk] = g_c[(n0 + a) * NK + k0 + kk];
            ssh[a][kk] = g_s[(n0 + a) * NK + k0 + kk];
        }
        if (isbf) {
            for (int i = tid; i < cnt * ND; i += 512) {
                int a = i >> 7, d = i & 127;
                hsh[a][d] = __bfloat162float(((const __nv_bfloat16*)P.h)[(long)(n0 + a) * ND + d]);
            }
        } else {
            const float4* h4 = (const float4*)P.h;
            for (int i = tid; i < cnt * 32; i += 512) {
                int a = i >> 5, dq = i & 31;
                ((float4*)&hsh[a][0])[dq] = h4[(long)(n0 + a) * 32 + dq];
            }
        }
        __syncthreads();
#pragma unroll 2
        for (int a = 0; a < cnt; a++) {
            float4 hv = *(const float4*)&hsh[a][d0];
            float c = csh[a][kq];
            float s = ssh[a][kq];
            aR[0] = fmaf(c, hv.x, aR[0]); aI[0] = fmaf(-s, hv.x, aI[0]);
            aR[1] = fmaf(c, hv.y, aR[1]); aI[1] = fmaf(-s, hv.y, aI[1]);
            aR[2] = fmaf(c, hv.z, aR[2]); aI[2] = fmaf(-s, hv.z, aI[2]);
            aR[3] = fmaf(c, hv.w, aR[3]); aI[3] = fmaf(-s, hv.w, aI[3]);
        }
        __syncthreads();
    }
    long off = ((long)b * NK + k0 + kq) * ND + d0;
    float4 f = *(const float4*)&g_F[off];
    float4 vR = make_float4(f.x * aR[0], f.y * aR[1], f.z * aR[2], f.w * aR[3]);
    float4 vI = make_float4(f.x * aI[0], f.y * aI[1], f.z * aI[2], f.w * aI[3]);
    *(float4*)&g_FSre[off] = vR;
    *(float4*)&g_FSim[off] = vI;
}

// ---------------------------------------------------------------------------
// out v2: grid (NB, 16), 256 threads, 16-atom chunks. Thread owns 2a x 4d.
// mode 0 = real fp32 | 1 = fp32 pairs | 2 = bf16 pairs
// ---------------------------------------------------------------------------
__global__ void __launch_bounds__(256) out_kernel(void* __restrict__ outp,
                                                  int mode, long cap) {
    int b = blockIdx.x;
    int s0 = g_seg[b], s1 = g_seg[b + 1];
    if (s1 < s0) s1 = s0;
    int tid = threadIdx.x;
    int d0 = (tid & 31) * 4;
    int a0 = (tid >> 5) * 2;          // warp-uniform

    __shared__ float csh[16][NK], ssh[16][NK];

    const float4* FR4 = (const float4*)(g_FSre + (long)b * NK * ND);
    const float4* FI4 = (const float4*)(g_FSim + (long)b * NK * ND);
    int dq = d0 >> 2;

    for (int n0 = s0 + blockIdx.y * 16; n0 < s1; n0 += 16 * 16) {
        int cnt = min(16, s1 - n0);
        for (int i = tid; i < cnt * NK; i += 256) {
            int a = i >> 7, k = i & 127;
            csh[a][k] = g_c[(n0 + a) * NK + k];
            ssh[a][k] = g_s[(n0 + a) * NK + k];
        }
        __syncthreads();

        if (mode == 0) {
            float oR0[4] = {0,0,0,0}, oR1[4] = {0,0,0,0};
#pragma unroll 4
            for (int k = 0; k < NK; k++) {
                float4 fr = FR4[k * 32 + dq];
                float4 fi = FI4[k * 32 + dq];
                float c0v = csh[a0][k],     s0v = ssh[a0][k];
                float c1v = csh[a0 + 1][k], s1v = ssh[a0 + 1][k];
                oR0[0] = fmaf(c0v, fr.x, fmaf(-s0v, fi.x, oR0[0]));
                oR0[1] = fmaf(c0v, fr.y, fmaf(-s0v, fi.y, oR0[1]));
                oR0[2] = fmaf(c0v, fr.z, fmaf(-s0v, fi.z, oR0[2]));
                oR0[3] = fmaf(c0v, fr.w, fmaf(-s0v, fi.w, oR0[3]));
                oR1[0] = fmaf(c1v, fr.x, fmaf(-s1v, fi.x, oR1[0]));
                oR1[1] = fmaf(c1v, fr.y, fmaf(-s1v, fi.y, oR1[1]));
                oR1[2] = fmaf(c1v, fr.z, fmaf(-s1v, fi.z, oR1[2]));
                oR1[3] = fmaf(c1v, fr.w, fmaf(-s1v, fi.w, oR1[3]));
            }
            for (int u = 0; u < 2; u++) {
                int a = a0 + u;
                if (a < cnt) {
                    long idx = (long)(n0 + a) * ND + d0;
                    if (idx + 4 <= cap) {
                        float* o = (float*)outp + idx;
                        float4 v = u == 0 ? make_float4(oR0[0], oR0[1], oR0[2], oR0[3])
                                          : make_float4(oR1[0], oR1[1], oR1[2], oR1[3]);
                        *(float4*)o = v;
                    }
                }
            }
        } else {
            float oR[2][4], oI[2][4];
#pragma unroll
            for (int u = 0; u < 2; u++)
#pragma unroll
                for (int i = 0; i < 4; i++) { oR[u][i] = 0.f; oI[u][i] = 0.f; }
#pragma unroll 2
            for (int k = 0; k < NK; k++) {
                float4 fr = FR4[k * 32 + dq];
                float4 fi = FI4[k * 32 + dq];
#pragma unroll
                for (int u = 0; u < 2; u++) {
                    float c = csh[a0 + u][k];
                    float s = ssh[a0 + u][k];
                    oR[u][0] = fmaf(c, fr.x, fmaf(-s, fi.x, oR[u][0]));
                    oR[u][1] = fmaf(c, fr.y, fmaf(-s, fi.y, oR[u][1]));
                    oR[u][2] = fmaf(c, fr.z, fmaf(-s, fi.z, oR[u][2]));
                    oR[u][3] = fmaf(c, fr.w, fmaf(-s, fi.w, oR[u][3]));
                    oI[u][0] = fmaf(s, fr.x, fmaf(c, fi.x, oI[u][0]));
                    oI[u][1] = fmaf(s, fr.y, fmaf(c, fi.y, oI[u][1]));
                    oI[u][2] = fmaf(s, fr.z, fmaf(c, fi.z, oI[u][2]));
                    oI[u][3] = fmaf(s, fr.w, fmaf(c, fi.w, oI[u][3]));
                }
            }
            for (int u = 0; u < 2; u++) {
                int a = a0 + u;
                if (a < cnt) {
                    long row = (long)(n0 + a) * ND;
                    for (int i = 0; i < 4; i++) {
                        long idx = row + d0 + i;
                        if (mode == 1) {
                            if (2 * idx + 1 < cap)
                                ((float2*)outp)[idx] = make_float2(oR[u][i], oI[u][i]);
                        } else {
                            if (idx + 1 <= cap) {
                                __nv_bfloat162 v;
                                v.x = __float2bfloat16(oR[u][i]);
                                v.y = __float2bfloat16(oI[u][i]);
                                ((__nv_bfloat162*)outp)[idx] = v;
                            }
                        }
                    }
                }
            }
        }
        __syncthreads();
    }
}

// ---------------------------------------------------------------------------
extern "C" void kernel_launch(void* const* d_in, const int* in_sizes, int n_in,
                              void* d_out, int out_size) {
    long mx = 0;
    for (int i = 0; i < n_in; i++) if ((long)in_sizes[i] > mx) mx = in_sizes[i];
    long mf;
    if (mx == 1048576L) mf = 1;
    else if (mx == 2097152L) mf = 2;
    else if (mx == 4194304L) mf = 4;
    else return;

    const void *kv = 0, *pos = 0, *h = 0, *W1 = 0;
    const void* bias[3] = {0, 0, 0};
    const void* grp[3] = {0, 0, 0};
    const void* extra = 0;
    int nb = 0, ng = 0;
    long extra_sz = (mf == 1) ? 8192 : (mf == 2) ? 65536 : 32768;
    for (int i = 0; i < n_in; i++) {
        long s = in_sizes[i];
        const void* p = d_in[i];
        if (s == 12288L * mf)        kv = p;
        else if (s == 24576L * mf)   pos = p;
        else if (s == 1048576L * mf) h = p;
        else if (s == 384L * mf)     W1 = p;
        else if (s == 128L * mf)   { if (nb < 3) bias[nb++] = p; }
        else if (s == 16384L * mf) { if (ng < 3) grp[ng++] = p; }
        else if (s == extra_sz)      extra = p;
    }
    if (!kv || !pos || !h || !W1 || nb < 3) return;

    const void *c0 = 0, *c1 = 0, *c2 = 0, *bd = 0;
    if (ng == 3)               { c0 = grp[0]; c1 = grp[1]; c2 = grp[2]; }
    else if (ng == 2 && extra) { c0 = grp[0]; c1 = grp[1]; bd = extra; }
    else return;

    int mode; long cap;
    if (out_size == 1048576)      { mode = 0; cap = 1048576L; }
    else if (out_size == 2097152) { mode = 1; cap = 2097152L; }
    else if (out_size == 8388608) { mode = 1; cap = 2097152L; }
    else if (out_size == 4194304) { mode = 2; cap = 1048576L; }
    else                          { mode = 0; cap = (long)out_size / 4; }

    long words = (long)out_size / 4;
    if (words > 0)
        zero_kernel<<<(int)((words + 255) / 256), 256>>>((unsigned int*)d_out, words);

    setup_kernel<<<1, 64>>>(kv, pos, h, W1, bias[0], bias[1], bias[2],
                            c0, c1, c2, bd, (int)mf);
    theta_kernel<<<NA, NK>>>();
    cudaFuncSetAttribute(mlp_kernel,
                         cudaFuncAttributeMaxDynamicSharedMemorySize, 65536);
    mlp_kernel<<<NB * NK / MLP_ROWS, 128, 65536>>>();
    segsum_kernel<<<dim3(NB, 8), 512>>>();
    out_kernel<<<dim3(NB, 16), 256>>>(d_out, mode, cap);
}

// round 12
// speedup vs baseline: 2.4673x; 1.1497x over previous
#include <cuda_runtime.h>
#include <cuda_bf16.h>
#include <math.h>

#define NA 8192
#define NB 32
#define NK 128
#define ND 128

__device__ float g_c[NA * NK];
__device__ float g_s[NA * NK];
__device__ float g_F[NB * NK * ND];
__device__ float g_FSre[NB * NK * ND];
__device__ float g_FSim[NB * NK * ND];
__device__ int   g_seg[NB + 1];

struct DevPtrs {
    const void *kv, *pos, *h, *W1, *b1, *W2, *b2, *W3, *b3, *batch;
    int isbf16;
    int batch64;
};
__device__ DevPtrs g_P;

__device__ __forceinline__ float ldf(const void* p, long i, int isbf) {
    if (isbf) return __bfloat162float(((const __nv_bfloat16*)p)[i]);
    return ((const float*)p)[i];
}
__device__ __forceinline__ int ldb(const void* p, int i, int b64) {
    if (b64) return (int)(((const long long*)p)[i]);
    return ((const int*)p)[i];
}
__device__ __forceinline__ float gelu_t(float x) {
    float x3 = x * x * x;
    return 0.5f * x * (1.0f + tanhf(0.7978845608028654f * fmaf(0.044715f, x3, x)));
}
__device__ static bool is_b32(const int* w) {
    int prev = -1;
    for (int j = 0; j < 128; j++) {
        int v = w[j];
        if (v < 0 || v > 63 || v < prev) return false;
        prev = v;
    }
    return true;
}
__device__ static bool is_b64(const int* w) {
    int prev = -1;
    for (int j = 0; j < 64; j++) {
        int lo = w[2*j], hi = w[2*j+1];
        if (hi != 0 || lo < 0 || lo > 63 || lo < prev) return false;
        prev = lo;
    }
    return true;
}

__global__ void setup_kernel(const void* kv, const void* pos, const void* h,
                             const void* W1, const void* b1, const void* b2,
                             const void* b3, const void* c0, const void* c1,
                             const void* c2, const void* batch_direct, int mf) {
    int tid = threadIdx.x;
    if (tid == 0) {
        DevPtrs P;
        P.kv = kv; P.pos = pos; P.h = h; P.W1 = W1;
        P.b1 = b1; P.b2 = b2; P.b3 = b3;
        const void* batch = batch_direct;
        const void* w2 = c0; const void* w3 = c1;
        if (!batch) {
            const void* cand[3] = {c0, c1, c2};
            int bi = -1;
            for (int i = 0; i < 3; i++) {
                const int* w = (const int*)cand[i];
                if (is_b32(w) || is_b64(w)) { bi = i; break; }
            }
            if (bi < 0) bi = 2;
            int nw = 0; const void* ws[2] = {0, 0};
            for (int i = 0; i < 3; i++) if (i != bi) ws[nw++] = cand[i];
            w2 = ws[0]; w3 = ws[1]; batch = cand[bi];
        }
        P.W2 = w2; P.W3 = w3; P.batch = batch;
        const int* bw = (const int*)batch;
        P.batch64 = (is_b64(bw) && !is_b32(bw)) ? 1 : 0;
        if (mf == 2) P.isbf16 = 1;
        else if (mf == 4) P.isbf16 = 0;
        else {
            const unsigned short* p16 = (const unsigned short*)pos;
            int hits = 0;
            for (int i = 0; i < 256; i++) {
                int e = (p16[i] >> 7) & 0xFF;
                if (e >= 110 && e <= 135) hits++;
            }
            P.isbf16 = (hits > 205);
        }
        g_P = P;
    }
    __syncthreads();
    if (tid <= NB) {
        const void* batch = g_P.batch;
        int b64 = g_P.batch64;
        int lo = 0, hi = NA;
        while (lo < hi) {
            int m = (lo + hi) >> 1;
            if (ldb(batch, m, b64) < tid) lo = m + 1; else hi = m;
        }
        if (lo < 0) lo = 0;
        if (lo > NA) lo = NA;
        g_seg[tid] = lo;
    }
}

__global__ void zero_kernel(unsigned int* out, long words) {
    long i = blockIdx.x * (long)blockDim.x + threadIdx.x;
    if (i < words) out[i] = 0u;
}

// ---------------------------------------------------------------------------
// theta: 2 atoms per block, 256 threads, MUFU sincos
// ---------------------------------------------------------------------------
__global__ void __launch_bounds__(256) theta_kernel() {
    const DevPtrs P = g_P;
    int n0 = blockIdx.x * 2;
    int tid = threadIdx.x;
    int a = tid >> 7;                 // 0..1
    int k = tid & 127;
    __shared__ float p[2][3];
    __shared__ int bsh[2];
    if (tid < 6) p[tid / 3][tid % 3] = ldf(P.pos, (long)n0 * 3 + tid, P.isbf16);
    if (tid < 2) bsh[tid] = ldb(P.batch, n0 + tid, P.batch64) & 31;
    __syncthreads();
    int n = n0 + a;
    long base = ((long)bsh[a] * NK + k) * 3;
    float th = fmaf(p[a][0], ldf(P.kv, base, P.isbf16),
               fmaf(p[a][1], ldf(P.kv, base + 1, P.isbf16),
                    p[a][2] * ldf(P.kv, base + 2, P.isbf16)));
    float sv, cv;
    __sincosf(th, &sv, &cv);
    g_c[n * NK + k] = cv;
    g_s[n * NK + k] = sv;
}

// ---------------------------------------------------------------------------
// MLP v3: 16 rows/block, 256 blocks, 256 threads (2 row-groups x 128 cols),
// 8 accumulators/thread, weights streamed from L1/L2.
// ---------------------------------------------------------------------------
#define MROWS 16
__global__ void __launch_bounds__(256) mlp_kernel() {
    __shared__ float a1[MROWS][NK];
    __shared__ float a2[MROWS][NK];
    __shared__ float kvs[MROWS * 3];

    const DevPtrs P = g_P;
    int isbf = P.isbf16;
    int row0 = blockIdx.x * MROWS;
    int tid = threadIdx.x;
    int t = tid & 127;
    int g = tid >> 7;                 // row group: rows g*8 .. g*8+7

    if (tid < MROWS * 3) kvs[tid] = ldf(P.kv, (long)row0 * 3 + tid, isbf);

    float w10 = ldf(P.W1, t, isbf);
    float w11 = ldf(P.W1, NK + t, isbf);
    float w12 = ldf(P.W1, 2 * NK + t, isbf);
    float bv1 = ldf(P.b1, t, isbf);
    __syncthreads();
#pragma unroll
    for (int r = 0; r < 8; r++) {
        int row = g * 8 + r;
        float x = fmaf(kvs[row*3], w10, fmaf(kvs[row*3+1], w11,
                  fmaf(kvs[row*3+2], w12, bv1)));
        a1[row][t] = gelu_t(x);
    }
    __syncthreads();

    // layer 2
    {
        float y[8];
        float bv = ldf(P.b2, t, isbf);
#pragma unroll
        for (int r = 0; r < 8; r++) y[r] = bv;
        for (int j = 0; j < NK; j += 4) {
            float w0 = ldf(P.W2, (long)j * NK + t, isbf);
            float w1 = ldf(P.W2, (long)(j+1) * NK + t, isbf);
            float w2 = ldf(P.W2, (long)(j+2) * NK + t, isbf);
            float w3 = ldf(P.W2, (long)(j+3) * NK + t, isbf);
#pragma unroll
            for (int r = 0; r < 8; r++) {
                float4 av = *(const float4*)&a1[g*8 + r][j];
                y[r] = fmaf(av.x, w0, y[r]);
                y[r] = fmaf(av.y, w1, y[r]);
                y[r] = fmaf(av.z, w2, y[r]);
                y[r] = fmaf(av.w, w3, y[r]);
            }
        }
#pragma unroll
        for (int r = 0; r < 8; r++) a2[g*8 + r][t] = gelu_t(y[r]);
    }
    __syncthreads();

    // layer 3
    {
        float y[8];
        float bv = ldf(P.b3, t, isbf);
#pragma unroll
        for (int r = 0; r < 8; r++) y[r] = bv;
        for (int j = 0; j < NK; j += 4) {
            float w0 = ldf(P.W3, (long)j * NK + t, isbf);
            float w1 = ldf(P.W3, (long)(j+1) * NK + t, isbf);
            float w2 = ldf(P.W3, (long)(j+2) * NK + t, isbf);
            float w3 = ldf(P.W3, (long)(j+3) * NK + t, isbf);
#pragma unroll
            for (int r = 0; r < 8; r++) {
                float4 av = *(const float4*)&a2[g*8 + r][j];
                y[r] = fmaf(av.x, w0, y[r]);
                y[r] = fmaf(av.y, w1, y[r]);
                y[r] = fmaf(av.z, w2, y[r]);
                y[r] = fmaf(av.w, w3, y[r]);
            }
        }
#pragma unroll
        for (int r = 0; r < 8; r++)
            g_F[(long)(row0 + g*8 + r) * NK + t] = y[r];
    }
}

// ---------------------------------------------------------------------------
// segsum v3: grid (NB, 4), 512 threads, thread owns 4d x 2k (32 k per block)
// ---------------------------------------------------------------------------
__global__ void __launch_bounds__(512) segsum_kernel() {
    const DevPtrs P = g_P;
    int isbf = P.isbf16;
    int b = blockIdx.x;
    int k0 = blockIdx.y * 32;
    int tid = threadIdx.x;
    int d0 = (tid & 31) * 4;
    int kq = tid >> 5;                // 0..15 -> k = k0 + kq*2 + {0,1}
    int s0 = g_seg[b], s1 = g_seg[b + 1];
    if (s1 < s0) s1 = s0;

    __shared__ float csh[32][32], ssh[32][32];
    __shared__ float hsh[32][ND];

    float aR[2][4], aI[2][4];
#pragma unroll
    for (int j = 0; j < 2; j++)
#pragma unroll
        for (int i = 0; i < 4; i++) { aR[j][i] = 0.f; aI[j][i] = 0.f; }

    for (int n0 = s0; n0 < s1; n0 += 32) {
        int cnt = min(32, s1 - n0);
        for (int i = tid; i < cnt * 32; i += 512) {
            int a = i >> 5, kk = i & 31;
            csh[a][kk] = g_c[(n0 + a) * NK + k0 + kk];
            ssh[a][kk] = g_s[(n0 + a) * NK + k0 + kk];
        }
        if (isbf) {
            for (int i = tid; i < cnt * ND; i += 512) {
                int a = i >> 7, d = i & 127;
                hsh[a][d] = __bfloat162float(((const __nv_bfloat16*)P.h)[(long)(n0 + a) * ND + d]);
            }
        } else {
            const float4* h4 = (const float4*)P.h;
            for (int i = tid; i < cnt * 32; i += 512) {
                int a = i >> 5, dq = i & 31;
                ((float4*)&hsh[a][0])[dq] = h4[(long)(n0 + a) * 32 + dq];
            }
        }
        __syncthreads();
#pragma unroll 2
        for (int a = 0; a < cnt; a++) {
            float4 hv = *(const float4*)&hsh[a][d0];
            float c0v = csh[a][kq*2],     s0v = ssh[a][kq*2];
            float c1v = csh[a][kq*2 + 1], s1v = ssh[a][kq*2 + 1];
            aR[0][0] = fmaf(c0v, hv.x, aR[0][0]); aI[0][0] = fmaf(-s0v, hv.x, aI[0][0]);
            aR[0][1] = fmaf(c0v, hv.y, aR[0][1]); aI[0][1] = fmaf(-s0v, hv.y, aI[0][1]);
            aR[0][2] = fmaf(c0v, hv.z, aR[0][2]); aI[0][2] = fmaf(-s0v, hv.z, aI[0][2]);
            aR[0][3] = fmaf(c0v, hv.w, aR[0][3]); aI[0][3] = fmaf(-s0v, hv.w, aI[0][3]);
            aR[1][0] = fmaf(c1v, hv.x, aR[1][0]); aI[1][0] = fmaf(-s1v, hv.x, aI[1][0]);
            aR[1][1] = fmaf(c1v, hv.y, aR[1][1]); aI[1][1] = fmaf(-s1v, hv.y, aI[1][1]);
            aR[1][2] = fmaf(c1v, hv.z, aR[1][2]); aI[1][2] = fmaf(-s1v, hv.z, aI[1][2]);
            aR[1][3] = fmaf(c1v, hv.w, aR[1][3]); aI[1][3] = fmaf(-s1v, hv.w, aI[1][3]);
        }
        __syncthreads();
    }
#pragma unroll
    for (int j = 0; j < 2; j++) {
        long off = ((long)b * NK + k0 + kq*2 + j) * ND + d0;
        float4 f = *(const float4*)&g_F[off];
        float4 vR = make_float4(f.x * aR[j][0], f.y * aR[j][1],
                                f.z * aR[j][2], f.w * aR[j][3]);
        float4 vI = make_float4(f.x * aI[j][0], f.y * aI[j][1],
                                f.z * aI[j][2], f.w * aI[j][3]);
        *(float4*)&g_FSre[off] = vR;
        *(float4*)&g_FSim[off] = vI;
    }
}

// ---------------------------------------------------------------------------
// out v3: grid (NB, 8), 256 threads, 32-atom tiles, thread owns 4a x 4d.
// mode 0 = real fp32 | 1 = fp32 pairs | 2 = bf16 pairs
// ---------------------------------------------------------------------------
__global__ void __launch_bounds__(256) out_kernel(void* __restrict__ outp,
                                                  int mode, long cap) {
    int b = blockIdx.x;
    int s0 = g_seg[b], s1 = g_seg[b + 1];
    if (s1 < s0) s1 = s0;
    int tid = threadIdx.x;
    int d0 = (tid & 31) * 4;
    int a0 = (tid >> 5) * 4;          // 8 warps x 4 atoms = 32

    __shared__ float csh[32][NK], ssh[32][NK];

    const float4* FR4 = (const float4*)(g_FSre + (long)b * NK * ND);
    const float4* FI4 = (const float4*)(g_FSim + (long)b * NK * ND);
    int dq = d0 >> 2;

    for (int n0 = s0 + blockIdx.y * 32; n0 < s1; n0 += 8 * 32) {
        int cnt = min(32, s1 - n0);
        for (int i = tid; i < cnt * 32; i += 256) {
            int a = i >> 5, kk = i & 31;
            ((float4*)&csh[a][0])[kk] = *(const float4*)&g_c[(n0 + a) * NK + kk*4];
            ((float4*)&ssh[a][0])[kk] = *(const float4*)&g_s[(n0 + a) * NK + kk*4];
        }
        __syncthreads();

        if (mode == 0) {
            float oR[4][4];
#pragma unroll
            for (int u = 0; u < 4; u++)
#pragma unroll
                for (int i = 0; i < 4; i++) oR[u][i] = 0.f;
#pragma unroll 2
            for (int k = 0; k < NK; k++) {
                float4 fr = FR4[k * 32 + dq];
                float4 fi = FI4[k * 32 + dq];
#pragma unroll
                for (int u = 0; u < 4; u++) {
                    float c = csh[a0 + u][k];
                    float s = ssh[a0 + u][k];
                    oR[u][0] = fmaf(c, fr.x, fmaf(-s, fi.x, oR[u][0]));
                    oR[u][1] = fmaf(c, fr.y, fmaf(-s, fi.y, oR[u][1]));
                    oR[u][2] = fmaf(c, fr.z, fmaf(-s, fi.z, oR[u][2]));
                    oR[u][3] = fmaf(c, fr.w, fmaf(-s, fi.w, oR[u][3]));
                }
            }
#pragma unroll
            for (int u = 0; u < 4; u++) {
                int a = a0 + u;
                if (a < cnt) {
                    long idx = (long)(n0 + a) * ND + d0;
                    if (idx + 4 <= cap)
                        *(float4*)((float*)outp + idx) =
                            make_float4(oR[u][0], oR[u][1], oR[u][2], oR[u][3]);
                }
            }
        } else {
            float oR[4][4], oI[4][4];
#pragma unroll
            for (int u = 0; u < 4; u++)
#pragma unroll
                for (int i = 0; i < 4; i++) { oR[u][i] = 0.f; oI[u][i] = 0.f; }
            for (int k = 0; k < NK; k++) {
                float4 fr = FR4[k * 32 + dq];
                float4 fi = FI4[k * 32 + dq];
#pragma unroll
                for (int u = 0; u < 4; u++) {
                    float c = csh[a0 + u][k];
                    float s = ssh[a0 + u][k];
                    oR[u][0] = fmaf(c, fr.x, fmaf(-s, fi.x, oR[u][0]));
                    oR[u][1] = fmaf(c, fr.y, fmaf(-s, fi.y, oR[u][1]));
                    oR[u][2] = fmaf(c, fr.z, fmaf(-s, fi.z, oR[u][2]));
                    oR[u][3] = fmaf(c, fr.w, fmaf(-s, fi.w, oR[u][3]));
                    oI[u][0] = fmaf(s, fr.x, fmaf(c, fi.x, oI[u][0]));
                    oI[u][1] = fmaf(s, fr.y, fmaf(c, fi.y, oI[u][1]));
                    oI[u][2] = fmaf(s, fr.z, fmaf(c, fi.z, oI[u][2]));
                    oI[u][3] = fmaf(s, fr.w, fmaf(c, fi.w, oI[u][3]));
                }
            }
            for (int u = 0; u < 4; u++) {
                int a = a0 + u;
                if (a < cnt) {
                    long row = (long)(n0 + a) * ND;
                    for (int i = 0; i < 4; i++) {
                        long idx = row + d0 + i;
                        if (mode == 1) {
                            if (2 * idx + 1 < cap)
                                ((float2*)outp)[idx] = make_float2(oR[u][i], oI[u][i]);
                        } else {
                            if (idx + 1 <= cap) {
                                __nv_bfloat162 v;
                                v.x = __float2bfloat16(oR[u][i]);
                                v.y = __float2bfloat16(oI[u][i]);
                                ((__nv_bfloat162*)outp)[idx] = v;
                            }
                        }
                    }
                }
            }
        }
        __syncthreads();
    }
}

// ---------------------------------------------------------------------------
extern "C" void kernel_launch(void* const* d_in, const int* in_sizes, int n_in,
                              void* d_out, int out_size) {
    long mx = 0;
    for (int i = 0; i < n_in; i++) if ((long)in_sizes[i] > mx) mx = in_sizes[i];
    long mf;
    if (mx == 1048576L) mf = 1;
    else if (mx == 2097152L) mf = 2;
    else if (mx == 4194304L) mf = 4;
    else return;

    const void *kv = 0, *pos = 0, *h = 0, *W1 = 0;
    const void* bias[3] = {0, 0, 0};
    const void* grp[3] = {0, 0, 0};
    const void* extra = 0;
    int nb = 0, ng = 0;
    long extra_sz = (mf == 1) ? 8192 : (mf == 2) ? 65536 : 32768;
    for (int i = 0; i < n_in; i++) {
        long s = in_sizes[i];
        const void* p = d_in[i];
        if (s == 12288L * mf)        kv = p;
        else if (s == 24576L * mf)   pos = p;
        else if (s == 1048576L * mf) h = p;
        else if (s == 384L * mf)     W1 = p;
        else if (s == 128L * mf)   { if (nb < 3) bias[nb++] = p; }
        else if (s == 16384L * mf) { if (ng < 3) grp[ng++] = p; }
        else if (s == extra_sz)      extra = p;
    }
    if (!kv || !pos || !h || !W1 || nb < 3) return;

    const void *c0 = 0, *c1 = 0, *c2 = 0, *bd = 0;
    if (ng == 3)               { c0 = grp[0]; c1 = grp[1]; c2 = grp[2]; }
    else if (ng == 2 && extra) { c0 = grp[0]; c1 = grp[1]; bd = extra; }
    else return;

    int mode; long cap;
    if (out_size == 1048576)      { mode = 0; cap = 1048576L; }
    else if (out_size == 2097152) { mode = 1; cap = 2097152L; }
    else if (out_size == 8388608) { mode = 1; cap = 2097152L; }
    else if (out_size == 4194304) { mode = 2; cap = 1048576L; }
    else                          { mode = 0; cap = (long)out_size / 4; }

    long words = (long)out_size / 4;
    if (words > 0)
        zero_kernel<<<(int)((words + 255) / 256), 256>>>((unsigned int*)d_out, words);

    setup_kernel<<<1, 64>>>(kv, pos, h, W1, bias[0], bias[1], bias[2],
                            c0, c1, c2, bd, (int)mf);
    theta_kernel<<<NA / 2, 256>>>();
    mlp_kernel<<<NB * NK / MROWS, 256>>>();
    segsum_kernel<<<dim3(NB, 4), 512>>>();
    out_kernel<<<dim3(NB, 8), 256>>>(d_out, mode, cap);
}